// round 2
// baseline (speedup 1.0000x reference)
#include <cuda_runtime.h>

// Grid geometry (fixed by the problem): N=2048
#define NE 2049   // E is NE x NE
#define NH 2048   // Hx cols / Hy rows
#define NW 2047   // Hx rows / Hy cols
#define CFLf 0.35f

// KF = [-11/6, 3, -3/2, 1/3], KB = [-1/3, 3/2, -3, 11/6]
#define KF0 (-11.0f/6.0f)
#define KF1 (3.0f)
#define KF2 (-1.5f)
#define KF3 (1.0f/3.0f)
#define KB0 (-1.0f/3.0f)
#define KB1 (1.5f)
#define KB2 (-3.0f)
#define KB3 (11.0f/6.0f)

// Combined 3x4 kernel M = beta*BETA + delta*DELTA + YEE + gamma*GAMMA
// Distinct values: a0 = m00=m03=m22, a1 = m02=m20=m23, plus m01, m11, m21.
__device__ __forceinline__ void load_M(float beta, float delta, float gamma,
                                       float& a0, float& a1,
                                       float& m01, float& m11, float& m21) {
    a0  = -0.25f * beta + 0.1f * gamma;
    a1  =  0.25f * beta - 0.1f * gamma;
    m01 =  0.25f * beta + delta - 0.5f - 0.1f * gamma;
    m11 = -2.0f * delta;
    m21 = -0.25f * beta + delta + 0.5f + 0.1f * gamma;
}

// ---------------------------------------------------------------------------
// Ampere: E_out(i,j) = E(i,j) + CFL*(s1(i,j) - s2(i,j)),  i,j in [0, NE)
// ---------------------------------------------------------------------------
__global__ __launch_bounds__(256)
void amper_kernel(const float* __restrict__ E,
                  const float* __restrict__ Hx,
                  const float* __restrict__ Hy,
                  const float* __restrict__ pb,
                  const float* __restrict__ pd,
                  const float* __restrict__ pg,
                  float* __restrict__ Eo) {
    const int j = blockIdx.x * 32 + (threadIdx.x & 31);
    const int i = blockIdx.y * 8 + (threadIdx.x >> 5);
    const int b = blockIdx.z;
    if (i >= NE || j >= NE) return;

    float a0, a1, m01, m11, m21;
    load_M(*pb, *pd, *pg, a0, a1, m01, m11, m21);

    const float* Eb  = E  + (size_t)b * NE * NE;
    const float* Hxb = Hx + (size_t)b * NW * NH;  // rows NW, cols NH
    const float* Hyb = Hy + (size_t)b * NH * NW;  // rows NH, cols NW

    const bool ic = (i >= 2 && i <= NE - 3);  // [2, 2046]
    const bool jc = (j >= 2 && j <= NE - 3);

    float s1 = 0.0f, s2 = 0.0f;

    if (ic && jc) {
        // s1 interior: sum_{p=0..3,q=0..2} Hy[i-2+p][j-2+q] * M[q][p]
        const float* r0 = Hyb + (size_t)(i - 2) * NW + (j - 2);
        const float* r1 = r0 + NW;
        const float* r2 = r1 + NW;
        const float* r3 = r2 + NW;
        s1 += a0  * r0[0] + a1  * r0[2]
            + m01 * r1[0] + m11 * r1[1] + m21 * r1[2]
            + a1  * r2[0] + a0  * r2[2]
            + a0  * r3[0] + a1  * r3[2];

        // s2 interior: sum_{p=0..2,q=0..3} Hx[i-2+p][j-2+q] * M[p][q]
        const float* x0 = Hxb + (size_t)(i - 2) * NH + (j - 2);
        const float* x1 = x0 + NH;
        const float* x2 = x1 + NH;
        s2 += a0 * x0[0] + m01 * x0[1] + a1 * x0[2] + a0 * x0[3]
            + m11 * x1[1]
            + a1 * x2[0] + m21 * x2[1] + a0 * x2[2] + a1 * x2[3];
    }

    // s1 KF: i in [1, 2048], j in [0, 2043]: Hy[i-1][j..j+3]
    if (i >= 1 && j <= NE - 6) {
        const float* r = Hyb + (size_t)(i - 1) * NW + j;
        s1 += KF0 * r[0] + KF1 * r[1] + KF2 * r[2] + KF3 * r[3];
    }
    // s1 KB: i in [0, 2047], j in [5, 2048]: Hy[i][j-5..j-2]
    if (i <= NE - 2 && j >= 5) {
        const float* r = Hyb + (size_t)i * NW + (j - 5);
        s1 += KB0 * r[0] + KB1 * r[1] + KB2 * r[2] + KB3 * r[3];
    }
    // s1 FU: i in [2,2046], j in {1,2}: Hy[i-1][j-1..j+2] * [-1,3,-3,1]
    if (ic && (j == 1 || j == 2)) {
        const float* r = Hyb + (size_t)(i - 1) * NW + (j - 1);
        s1 += -r[0] + 3.0f * r[1] - 3.0f * r[2] + r[3];
    }
    // s1 FD: i in [2,2046], j in {2046,2047}: Hy[i][j-4..j-1] * [1,-3,3,-1]
    if (ic && (j == NE - 3 || j == NE - 2)) {
        const float* r = Hyb + (size_t)i * NW + (j - 4);
        s1 += r[0] - 3.0f * r[1] + 3.0f * r[2] - r[3];
    }

    // s2 KF: i in [0, 2043], j in [1, 2048]: Hx[i..i+3][j-1]
    if (i <= NE - 6 && j >= 1) {
        const float* x = Hxb + (size_t)i * NH + (j - 1);
        s2 += KF0 * x[0] + KF1 * x[NH] + KF2 * x[2 * NH] + KF3 * x[3 * NH];
    }
    // s2 KB: i in [5, 2048], j in [0, 2047]: Hx[i-5..i-2][j]
    if (i >= 5 && j <= NE - 2) {
        const float* x = Hxb + (size_t)(i - 5) * NH + j;
        s2 += KB0 * x[0] + KB1 * x[NH] + KB2 * x[2 * NH] + KB3 * x[3 * NH];
    }
    // s2 FU: i in {1,2}, j in [2,2046]: Hx[i-1..i+2][j-1] * [-1,3,-3,1]
    if ((i == 1 || i == 2) && jc) {
        const float* x = Hxb + (size_t)(i - 1) * NH + (j - 1);
        s2 += -x[0] + 3.0f * x[NH] - 3.0f * x[2 * NH] + x[3 * NH];
    }
    // s2 FD: i in {2046,2047}, j in [2,2046]: Hx[i-4..i-1][j] * [1,-3,3,-1]
    if ((i == NE - 3 || i == NE - 2) && jc) {
        const float* x = Hxb + (size_t)(i - 4) * NH + j;
        s2 += x[0] - 3.0f * x[NH] + 3.0f * x[2 * NH] - x[3 * NH];
    }

    Eo[(size_t)b * NE * NE + (size_t)i * NE + j] =
        Eb[(size_t)i * NE + j] + CFLf * (s1 - s2);
}

// ---------------------------------------------------------------------------
// Faraday (fused Hx + Hy update):
//   Hx_out(i,j) = Hx - CFL*s3,  i in [0, NW), j in [0, NH)
//   Hy_out(i,j) = Hy + CFL*s4,  i in [0, NH), j in [0, NW)
// ---------------------------------------------------------------------------
__global__ __launch_bounds__(256)
void faraday_kernel(const float* __restrict__ E,
                    const float* __restrict__ Hx,
                    const float* __restrict__ Hy,
                    const float* __restrict__ pb,
                    const float* __restrict__ pd,
                    const float* __restrict__ pg,
                    float* __restrict__ Hxo,
                    float* __restrict__ Hyo) {
    const int j = blockIdx.x * 32 + (threadIdx.x & 31);
    const int i = blockIdx.y * 8 + (threadIdx.x >> 5);
    const int b = blockIdx.z;
    if (i >= NH || j >= NH) return;

    float a0, a1, m01, m11, m21;
    load_M(*pb, *pd, *pg, a0, a1, m01, m11, m21);

    const float* Eb = E + (size_t)b * NE * NE;

    // ---- Hx update ----
    if (i < NW) {
        float s3 = 0.0f;
        // interior: j in [1, 2046]: sum_{p,q} E[i+p][j-1+q] * M[p][q]
        if (j >= 1 && j <= NH - 2) {
            const float* e0 = Eb + (size_t)i * NE + (j - 1);
            const float* e1 = e0 + NE;
            const float* e2 = e1 + NE;
            s3 += a0 * e0[0] + m01 * e0[1] + a1 * e0[2] + a0 * e0[3]
                + m11 * e1[1]
                + a1 * e2[0] + m21 * e2[1] + a0 * e2[2] + a1 * e2[3];
        }
        // KEF: i <= 2044: -1.5*E[i+1][j] + 2*E[i+2][j] - 0.5*E[i+3][j]
        if (i <= NH - 4) {
            const float* e = Eb + (size_t)(i + 1) * NE + j;
            s3 += -1.5f * e[0] + 2.0f * e[NE] - 0.5f * e[2 * NE];
        }
        // KEB: i >= 2: 0.5*E[i-1][j+1] - 2*E[i][j+1] + 1.5*E[i+1][j+1]
        if (i >= 2) {
            const float* e = Eb + (size_t)(i - 1) * NE + (j + 1);
            s3 += 0.5f * e[0] - 2.0f * e[NE] + 1.5f * e[2 * NE];
        }
        const size_t off = (size_t)b * NW * NH + (size_t)i * NH + j;
        Hxo[off] = Hx[off] - CFLf * s3;
    }

    // ---- Hy update ----
    if (j < NW) {
        float s4 = 0.0f;
        // interior: i in [1, 2046]: sum_{p,q} E[i-1+p][j+q] * M[q][p]
        if (i >= 1 && i <= NH - 2) {
            const float* e0 = Eb + (size_t)(i - 1) * NE + j;
            const float* e1 = e0 + NE;
            const float* e2 = e1 + NE;
            const float* e3 = e2 + NE;
            s4 += a0  * e0[0] + a1  * e0[2]
                + m01 * e1[0] + m11 * e1[1] + m21 * e1[2]
                + a1  * e2[0] + a0  * e2[2]
                + a0  * e3[0] + a1  * e3[2];
        }
        // KEF^T: j <= 2044: -1.5*E[i][j+1] + 2*E[i][j+2] - 0.5*E[i][j+3]
        if (j <= NH - 4) {
            const float* e = Eb + (size_t)i * NE + (j + 1);
            s4 += -1.5f * e[0] + 2.0f * e[1] - 0.5f * e[2];
        }
        // KEB^T: j >= 2: 0.5*E[i+1][j-1] - 2*E[i+1][j] + 1.5*E[i+1][j+1]
        if (j >= 2) {
            const float* e = Eb + (size_t)(i + 1) * NE + (j - 1);
            s4 += 0.5f * e[0] - 2.0f * e[1] + 1.5f * e[2];
        }
        const size_t off = (size_t)b * NH * NW + (size_t)i * NW + j;
        Hyo[off] = Hy[off] + CFLf * s4;
    }
}

extern "C" void kernel_launch(void* const* d_in, const int* in_sizes, int n_in,
                              void* d_out, int out_size) {
    const float* E0  = (const float*)d_in[0];
    const float* Hx0 = (const float*)d_in[1];
    const float* Hy0 = (const float*)d_in[2];
    const float* pb  = (const float*)d_in[3];
    const float* pd  = (const float*)d_in[4];
    const float* pg  = (const float*)d_in[5];

    const int B = in_sizes[0] / (NE * NE);

    const size_t nE  = (size_t)B * NE * NE;
    const size_t nHx = (size_t)B * NW * NH;
    const size_t nHy = (size_t)B * NH * NW;

    float* out = (float*)d_out;
    float* E2  = out;
    float* Hx2 = E2 + nE;
    float* Hy2 = Hx2 + nHx;
    float* E3  = Hy2 + nHy;
    float* Hx3 = E3 + nE;
    float* Hy3 = Hx3 + nHx;
    float* E4  = Hy3 + nHy;
    float* Hx4 = E4 + nE;
    float* Hy4 = Hx4 + nHx;

    dim3 blk(256);
    dim3 gA((NE + 31) / 32, (NE + 7) / 8, B);
    dim3 gF((NH + 31) / 32, (NH + 7) / 8, B);

    // Step 1
    amper_kernel<<<gA, blk>>>(E0, Hx0, Hy0, pb, pd, pg, E2);
    faraday_kernel<<<gF, blk>>>(E2, Hx0, Hy0, pb, pd, pg, Hx2, Hy2);
    // Step 2
    amper_kernel<<<gA, blk>>>(E2, Hx2, Hy2, pb, pd, pg, E3);
    faraday_kernel<<<gF, blk>>>(E3, Hx2, Hy2, pb, pd, pg, Hx3, Hy3);
    // Step 3
    amper_kernel<<<gA, blk>>>(E3, Hx3, Hy3, pb, pd, pg, E4);
    faraday_kernel<<<gF, blk>>>(E4, Hx3, Hy3, pb, pd, pg, Hx4, Hy4);
}

// round 4
// speedup vs baseline: 1.6916x; 1.6916x over previous
#include <cuda_runtime.h>

#define NE 2049   // E is NE x NE
#define NH 2048   // Hx cols / Hy rows
#define NW 2047   // Hx rows / Hy cols
#define CFLf 0.35f

#define KF0 (-11.0f/6.0f)
#define KF1 (3.0f)
#define KF2 (-1.5f)
#define KF3 (1.0f/3.0f)
#define KB0 (-1.0f/3.0f)
#define KB1 (1.5f)
#define KB2 (-3.0f)
#define KB3 (11.0f/6.0f)

__device__ __forceinline__ void load_M(float beta, float delta, float gamma,
                                       float& a0, float& a1,
                                       float& m01, float& m11, float& m21) {
    a0  = -0.25f * beta + 0.1f * gamma;
    a1  =  0.25f * beta - 0.1f * gamma;
    m01 =  0.25f * beta + delta - 0.5f - 0.1f * gamma;
    m11 = -2.0f * delta;
    m21 = -0.25f * beta + delta + 0.5f + 0.1f * gamma;
}

// ===========================================================================
// Scalar point functions (verified in R1) — used for boundary strips.
// ===========================================================================
__device__ void amper_point(int i, int j,
                            const float* __restrict__ Eb,
                            const float* __restrict__ Hxb,
                            const float* __restrict__ Hyb,
                            float a0, float a1, float m01, float m11, float m21,
                            float* __restrict__ Eob) {
    const bool ic = (i >= 2 && i <= NE - 3);
    const bool jc = (j >= 2 && j <= NE - 3);
    float s1 = 0.0f, s2 = 0.0f;

    if (ic && jc) {
        const float* r0 = Hyb + (size_t)(i - 2) * NW + (j - 2);
        const float* r1 = r0 + NW;
        const float* r2 = r1 + NW;
        const float* r3 = r2 + NW;
        s1 += a0  * r0[0] + a1  * r0[2]
            + m01 * r1[0] + m11 * r1[1] + m21 * r1[2]
            + a1  * r2[0] + a0  * r2[2]
            + a0  * r3[0] + a1  * r3[2];
        const float* x0 = Hxb + (size_t)(i - 2) * NH + (j - 2);
        const float* x1 = x0 + NH;
        const float* x2 = x1 + NH;
        s2 += a0 * x0[0] + m01 * x0[1] + a1 * x0[2] + a0 * x0[3]
            + m11 * x1[1]
            + a1 * x2[0] + m21 * x2[1] + a0 * x2[2] + a1 * x2[3];
    }
    if (i >= 1 && j <= NE - 6) {
        const float* r = Hyb + (size_t)(i - 1) * NW + j;
        s1 += KF0 * r[0] + KF1 * r[1] + KF2 * r[2] + KF3 * r[3];
    }
    if (i <= NE - 2 && j >= 5) {
        const float* r = Hyb + (size_t)i * NW + (j - 5);
        s1 += KB0 * r[0] + KB1 * r[1] + KB2 * r[2] + KB3 * r[3];
    }
    if (ic && (j == 1 || j == 2)) {
        const float* r = Hyb + (size_t)(i - 1) * NW + (j - 1);
        s1 += -r[0] + 3.0f * r[1] - 3.0f * r[2] + r[3];
    }
    if (ic && (j == NE - 3 || j == NE - 2)) {
        const float* r = Hyb + (size_t)i * NW + (j - 4);
        s1 += r[0] - 3.0f * r[1] + 3.0f * r[2] - r[3];
    }
    if (i <= NE - 6 && j >= 1) {
        const float* x = Hxb + (size_t)i * NH + (j - 1);
        s2 += KF0 * x[0] + KF1 * x[NH] + KF2 * x[2 * NH] + KF3 * x[3 * NH];
    }
    if (i >= 5 && j <= NE - 2) {
        const float* x = Hxb + (size_t)(i - 5) * NH + j;
        s2 += KB0 * x[0] + KB1 * x[NH] + KB2 * x[2 * NH] + KB3 * x[3 * NH];
    }
    if ((i == 1 || i == 2) && jc) {
        const float* x = Hxb + (size_t)(i - 1) * NH + (j - 1);
        s2 += -x[0] + 3.0f * x[NH] - 3.0f * x[2 * NH] + x[3 * NH];
    }
    if ((i == NE - 3 || i == NE - 2) && jc) {
        const float* x = Hxb + (size_t)(i - 4) * NH + j;
        s2 += x[0] - 3.0f * x[NH] + 3.0f * x[2 * NH] - x[3 * NH];
    }
    Eob[(size_t)i * NE + j] = Eb[(size_t)i * NE + j] + CFLf * (s1 - s2);
}

__device__ void faraday_point(int i, int j,
                              const float* __restrict__ Eb,
                              const float* __restrict__ Hxb,
                              const float* __restrict__ Hyb,
                              float a0, float a1, float m01, float m11, float m21,
                              float* __restrict__ Hxob,
                              float* __restrict__ Hyob) {
    if (i < NW && j < NH) {
        float s3 = 0.0f;
        if (j >= 1 && j <= NH - 2) {
            const float* e0 = Eb + (size_t)i * NE + (j - 1);
            const float* e1 = e0 + NE;
            const float* e2 = e1 + NE;
            s3 += a0 * e0[0] + m01 * e0[1] + a1 * e0[2] + a0 * e0[3]
                + m11 * e1[1]
                + a1 * e2[0] + m21 * e2[1] + a0 * e2[2] + a1 * e2[3];
        }
        if (i <= NH - 4) {
            const float* e = Eb + (size_t)(i + 1) * NE + j;
            s3 += -1.5f * e[0] + 2.0f * e[NE] - 0.5f * e[2 * NE];
        }
        if (i >= 2) {
            const float* e = Eb + (size_t)(i - 1) * NE + (j + 1);
            s3 += 0.5f * e[0] - 2.0f * e[NE] + 1.5f * e[2 * NE];
        }
        const size_t off = (size_t)i * NH + j;
        Hxob[off] = Hxb[off] - CFLf * s3;
    }
    if (i < NH && j < NW) {
        float s4 = 0.0f;
        if (i >= 1 && i <= NH - 2) {
            const float* e0 = Eb + (size_t)(i - 1) * NE + j;
            const float* e1 = e0 + NE;
            const float* e2 = e1 + NE;
            const float* e3 = e2 + NE;
            s4 += a0  * e0[0] + a1  * e0[2]
                + m01 * e1[0] + m11 * e1[1] + m21 * e1[2]
                + a1  * e2[0] + a0  * e2[2]
                + a0  * e3[0] + a1  * e3[2];
        }
        if (j <= NH - 4) {
            const float* e = Eb + (size_t)i * NE + (j + 1);
            s4 += -1.5f * e[0] + 2.0f * e[1] - 0.5f * e[2];
        }
        if (j >= 2) {
            const float* e = Eb + (size_t)(i + 1) * NE + (j - 1);
            s4 += 0.5f * e[0] - 2.0f * e[1] + 1.5f * e[2];
        }
        const size_t off = (size_t)i * NW + j;
        Hyob[off] = Hyb[off] + CFLf * s4;
    }
}

// ===========================================================================
// Interior amper: i in [5, 2036] (254 blocks of IT=8), j in [5, 2043].
// Scatter formulation: sweep Hy rows (i0-2 .. i0+8) and Hx rows (i0-5 .. i0+10),
// registers carry 8 accumulators.
// ===========================================================================
#define IT 8

__global__ __launch_bounds__(256)
void amper_int_kernel(const float* __restrict__ E,
                      const float* __restrict__ Hx,
                      const float* __restrict__ Hy,
                      const float* __restrict__ pb,
                      const float* __restrict__ pd,
                      const float* __restrict__ pg,
                      float* __restrict__ Eo) {
    const int j = 5 + blockIdx.x * 256 + threadIdx.x;
    if (j > 2043) return;
    const int i0 = 5 + blockIdx.y * IT;
    const int b = blockIdx.z;

    float a0, a1, m01, m11, m21;
    load_M(*pb, *pd, *pg, a0, a1, m01, m11, m21);
    const float a1k  = a1 + KB3;   // merged a1 + KB3 (same accumulator)
    const float m21k = m21 + KF0;  // merged m21 + KF0

    const float* Eb  = E  + (size_t)b * NE * NE;
    const float* Hxb = Hx + (size_t)b * NW * NH;
    const float* Hyb = Hy + (size_t)b * NH * NW;
    float* Eob = Eo + (size_t)b * NE * NE;

    float acc[IT];
#pragma unroll
    for (int k = 0; k < IT; k++) acc[k] = 0.0f;

    // ---- s1: Hy rows r = i0-2 .. i0+8, cols j-5 .. j+3 ----
    {
        const float* hy = Hyb + (size_t)(i0 - 2) * NW + (j - 5);
#pragma unroll
        for (int rr = 0; rr < IT + 3; ++rr) {
            const bool uA = (rr <= IT - 1);              // k=rr   : a0*c3 + a1*c5
            const bool uB = (rr >= 1 && rr <= IT);       // k=rr-1 : interior p1 + KF
            const bool uC = (rr >= 2 && rr <= IT + 1);   // k=rr-2 : interior p2 + KB
            const bool uD = (rr >= 3);                   // k=rr-3 : a0*c3 + a1*c5
            float c0 = 0.f, c1 = 0.f, c2 = 0.f, c4 = 0.f, c6 = 0.f, c7 = 0.f, c8 = 0.f;
            const float c3 = hy[3];
            const float c5 = hy[5];
            if (uC) { c0 = hy[0]; c1 = hy[1]; c2 = hy[2]; }
            if (uB) { c4 = hy[4]; c6 = hy[6]; c7 = hy[7]; c8 = hy[8]; }
            const float t = a0 * c3 + a1 * c5;
            if (uA) acc[rr]     += t;
            if (uB) acc[rr - 1] += m01 * c3 + m11 * c4 + m21k * c5
                                 + KF1 * c6 + KF2 * c7 + KF3 * c8;
            if (uC) acc[rr - 2] += KB0 * c0 + KB1 * c1 + KB2 * c2
                                 + a1k * c3 + a0 * c5;
            if (uD) acc[rr - 3] += t;
            hy += NW;
        }
    }

    // ---- s2 (subtract): Hx rows r = i0-5 .. i0+10, cols j-2 .. j+1 ----
    {
        const float* hx = Hxb + (size_t)(i0 - 5) * NH + (j - 2);
#pragma unroll
        for (int rr = 0; rr < IT + 8; ++rr) {
            const bool vK0 = (rr <= IT - 1);                 // k=rr   : KB0*d2
            const bool vK1 = (rr >= 1 && rr <= IT);          // k=rr-1 : KB1*d2
            const bool vK2 = (rr >= 2 && rr <= IT + 1);      // k=rr-2 : KB2*d2
            const bool vA  = (rr >= 3 && rr <= IT + 2);      // k=rr-3 : p0 + KB3
            const bool vB  = (rr >= 4 && rr <= IT + 3);      // k=rr-4 : m11*d1
            const bool vC  = (rr >= 5 && rr <= IT + 4);      // k=rr-5 : p2 + KF0
            const bool vD  = (rr >= 6 && rr <= IT + 5);      // k=rr-6 : KF1*d1
            const bool vE  = (rr >= 7 && rr <= IT + 6);      // k=rr-7 : KF2*d1
            const bool vF  = (rr >= 8);                      // k=rr-8 : KF3*d1
            float d0 = 0.f, d1 = 0.f, d2 = 0.f, d3 = 0.f;
            if (vA | vC) { d0 = hx[0]; d3 = hx[3]; }
            if (vA | vB | vC | vD | vE | vF) d1 = hx[1];
            if (vK0 | vK1 | vK2 | vA | vC) d2 = hx[2];
            if (vK0) acc[rr]     -= KB0 * d2;
            if (vK1) acc[rr - 1] -= KB1 * d2;
            if (vK2) acc[rr - 2] -= KB2 * d2;
            if (vA)  acc[rr - 3] -= a0 * d0 + m01 * d1 + a1k * d2 + a0 * d3;
            if (vB)  acc[rr - 4] -= m11 * d1;
            if (vC)  acc[rr - 5] -= a1 * d0 + m21k * d1 + a0 * d2 + a1 * d3;
            if (vD)  acc[rr - 6] -= KF1 * d1;
            if (vE)  acc[rr - 7] -= KF2 * d1;
            if (vF)  acc[rr - 8] -= KF3 * d1;
            hx += NH;
        }
    }

    const size_t off = (size_t)i0 * NE + j;
#pragma unroll
    for (int k = 0; k < IT; k++)
        Eob[off + (size_t)k * NE] = Eb[off + (size_t)k * NE] + CFLf * acc[k];
}

// ===========================================================================
// Interior faraday (fused Hx+Hy): i in [2, 2041] (255 blocks), j in [2, 2044].
// Sweep E rows r = i0-1 .. i0+10, cols j-1 .. j+3.
// ===========================================================================
__global__ __launch_bounds__(256)
void faraday_int_kernel(const float* __restrict__ E,
                        const float* __restrict__ Hx,
                        const float* __restrict__ Hy,
                        const float* __restrict__ pb,
                        const float* __restrict__ pd,
                        const float* __restrict__ pg,
                        float* __restrict__ Hxo,
                        float* __restrict__ Hyo) {
    const int j = 2 + blockIdx.x * 256 + threadIdx.x;
    if (j > 2044) return;
    const int i0 = 2 + blockIdx.y * IT;
    const int b = blockIdx.z;

    float a0, a1, m01, m11, m21;
    load_M(*pb, *pd, *pg, a0, a1, m01, m11, m21);
    const float m11b = m11 - 1.5f;  // m11 + KEF row-merge
    const float m21b = m21 + 2.0f;  // m21 + KEF row-merge
    const float a1m2 = a1 - 2.0f;   // a1 + KEB middle coeff

    const float* Eb = E + (size_t)b * NE * NE;

    float sx[IT], sy[IT];
#pragma unroll
    for (int k = 0; k < IT; k++) { sx[k] = 0.0f; sy[k] = 0.0f; }

    const float* ep = Eb + (size_t)(i0 - 1) * NE + (j - 1);
#pragma unroll
    for (int rr = 0; rr < IT + 4; ++rr) {
        const bool w0 = (rr <= IT - 1);               // k=rr
        const bool w1 = (rr >= 1 && rr <= IT);        // k=rr-1
        const bool w2 = (rr >= 2 && rr <= IT + 1);    // k=rr-2
        const bool w3 = (rr >= 3 && rr <= IT + 2);    // k=rr-3
        const bool w4 = (rr >= 4);                    // k=rr-4 (Hx only)
        float e0 = 0.f, e2 = 0.f, e3 = 0.f, e4 = 0.f;
        const float e1 = ep[1];
        if (w1 | w2 | w3) e0 = ep[0];
        if (w0 | w1 | w2 | w3) { e2 = ep[2]; e3 = ep[3]; }
        if (w1) e4 = ep[4];

        const float ty = a0 * e1 + a1 * e3;  // shared by w0 and w3 (Hy)
        if (w0) { sx[rr] += 0.5f * e2; sy[rr] += ty; }
        if (w1) {
            sx[rr - 1] += a0 * e0 + m01 * e1 + a1m2 * e2 + a0 * e3;
            sy[rr - 1] += m01 * e1 + m11b * e2 + m21b * e3 - 0.5f * e4;
        }
        if (w2) {
            sx[rr - 2] += m11b * e1 + 1.5f * e2;
            sy[rr - 2] += 0.5f * e0 + a1m2 * e1 + 1.5f * e2 + a0 * e3;
        }
        if (w3) {
            sx[rr - 3] += a1 * e0 + m21b * e1 + a0 * e2 + a1 * e3;
            sy[rr - 3] += ty;
        }
        if (w4) sx[rr - 4] -= 0.5f * e1;
        ep += NE;
    }

    const size_t offx = (size_t)b * NW * NH + (size_t)i0 * NH + j;
    const size_t offy = (size_t)b * NH * NW + (size_t)i0 * NW + j;
#pragma unroll
    for (int k = 0; k < IT; k++) {
        Hxo[offx + (size_t)k * NH] = Hx[offx + (size_t)k * NH] - CFLf * sx[k];
        Hyo[offy + (size_t)k * NW] = Hy[offy + (size_t)k * NW] + CFLf * sy[k];
    }
}

// ===========================================================================
// Boundary kernels (thin strips, scalar point functions).
// ===========================================================================
// amper boundary: y in [0,17): row strips i in {0..4} u {2037..2048}, all j
//                 y in [17,27): col strips j in {0..4} u {2044..2048}, i in [5,2036]
__global__ __launch_bounds__(256)
void amper_bnd_kernel(const float* __restrict__ E,
                      const float* __restrict__ Hx,
                      const float* __restrict__ Hy,
                      const float* __restrict__ pb,
                      const float* __restrict__ pd,
                      const float* __restrict__ pg,
                      float* __restrict__ Eo) {
    const int b = blockIdx.z;
    float a0, a1, m01, m11, m21;
    load_M(*pb, *pd, *pg, a0, a1, m01, m11, m21);
    const float* Eb  = E  + (size_t)b * NE * NE;
    const float* Hxb = Hx + (size_t)b * NW * NH;
    const float* Hyb = Hy + (size_t)b * NH * NW;
    float* Eob = Eo + (size_t)b * NE * NE;

    const int y = blockIdx.y;
    if (y < 17) {
        const int i = (y < 5) ? y : 2037 + (y - 5);
        const int j = blockIdx.x * 256 + threadIdx.x;
        if (j >= NE) return;
        amper_point(i, j, Eb, Hxb, Hyb, a0, a1, m01, m11, m21, Eob);
    } else {
        const int c = y - 17;
        const int j = (c < 5) ? c : 2044 + (c - 5);
        const int i = 5 + blockIdx.x * 256 + threadIdx.x;
        if (i > 2036) return;
        amper_point(i, j, Eb, Hxb, Hyb, a0, a1, m01, m11, m21, Eob);
    }
}

// faraday boundary: y in [0,8): row strips i in {0,1} u {2042..2047}, all j
//                   y in [8,13): col strips j in {0,1} u {2045..2047}, i in [2,2041]
__global__ __launch_bounds__(256)
void faraday_bnd_kernel(const float* __restrict__ E,
                        const float* __restrict__ Hx,
                        const float* __restrict__ Hy,
                        const float* __restrict__ pb,
                        const float* __restrict__ pd,
                        const float* __restrict__ pg,
                        float* __restrict__ Hxo,
                        float* __restrict__ Hyo) {
    const int b = blockIdx.z;
    float a0, a1, m01, m11, m21;
    load_M(*pb, *pd, *pg, a0, a1, m01, m11, m21);
    const float* Eb  = E  + (size_t)b * NE * NE;
    const float* Hxb = Hx + (size_t)b * NW * NH;
    const float* Hyb = Hy + (size_t)b * NH * NW;
    float* Hxob = Hxo + (size_t)b * NW * NH;
    float* Hyob = Hyo + (size_t)b * NH * NW;

    const int y = blockIdx.y;
    if (y < 8) {
        const int i = (y < 2) ? y : 2042 + (y - 2);
        const int j = blockIdx.x * 256 + threadIdx.x;
        if (j >= NH) return;
        faraday_point(i, j, Eb, Hxb, Hyb, a0, a1, m01, m11, m21, Hxob, Hyob);
    } else {
        const int c = y - 8;
        const int j = (c < 2) ? c : 2045 + (c - 2);
        const int i = 2 + blockIdx.x * 256 + threadIdx.x;
        if (i > 2041) return;
        faraday_point(i, j, Eb, Hxb, Hyb, a0, a1, m01, m11, m21, Hxob, Hyob);
    }
}

// ===========================================================================
extern "C" void kernel_launch(void* const* d_in, const int* in_sizes, int n_in,
                              void* d_out, int out_size) {
    const float* E0  = (const float*)d_in[0];
    const float* Hx0 = (const float*)d_in[1];
    const float* Hy0 = (const float*)d_in[2];
    const float* pb  = (const float*)d_in[3];
    const float* pd  = (const float*)d_in[4];
    const float* pg  = (const float*)d_in[5];

    const int B = in_sizes[0] / (NE * NE);

    const size_t nE  = (size_t)B * NE * NE;
    const size_t nHx = (size_t)B * NW * NH;
    const size_t nHy = (size_t)B * NH * NW;

    float* out = (float*)d_out;
    float* E2  = out;
    float* Hx2 = E2 + nE;
    float* Hy2 = Hx2 + nHx;
    float* E3  = Hy2 + nHy;
    float* Hx3 = E3 + nE;
    float* Hy3 = Hx3 + nHx;
    float* E4  = Hy3 + nHy;
    float* Hx4 = E4 + nE;
    float* Hy4 = Hx4 + nHx;

    dim3 blk(256);
    dim3 gAi(8, 254, B);    // amper interior: j in [5,2043], i0 = 5 + 8*y
    dim3 gAb(9, 27, B);     // amper boundary
    dim3 gFi(8, 255, B);    // faraday interior: j in [2,2044], i0 = 2 + 8*y
    dim3 gFb(8, 13, B);     // faraday boundary

    const float* Ein  = E0;
    const float* Hxin = Hx0;
    const float* Hyin = Hy0;
    float* Eouts[3]  = {E2, E3, E4};
    float* Hxouts[3] = {Hx2, Hx3, Hx4};
    float* Hyouts[3] = {Hy2, Hy3, Hy4};

    for (int s = 0; s < 3; s++) {
        amper_int_kernel<<<gAi, blk>>>(Ein, Hxin, Hyin, pb, pd, pg, Eouts[s]);
        amper_bnd_kernel<<<gAb, blk>>>(Ein, Hxin, Hyin, pb, pd, pg, Eouts[s]);
        faraday_int_kernel<<<gFi, blk>>>(Eouts[s], Hxin, Hyin, pb, pd, pg,
                                         Hxouts[s], Hyouts[s]);
        faraday_bnd_kernel<<<gFb, blk>>>(Eouts[s], Hxin, Hyin, pb, pd, pg,
                                         Hxouts[s], Hyouts[s]);
        Ein = Eouts[s]; Hxin = Hxouts[s]; Hyin = Hyouts[s];
    }
}

// round 5
// speedup vs baseline: 1.8844x; 1.1140x over previous
#include <cuda_runtime.h>

#define NE 2049   // E is NE x NE
#define NH 2048   // Hx cols / Hy rows
#define NW 2047   // Hx rows / Hy cols
#define CFLf 0.35f

#define KF0 (-11.0f/6.0f)
#define KF1 (3.0f)
#define KF2 (-1.5f)
#define KF3 (1.0f/3.0f)
#define KB0 (-1.0f/3.0f)
#define KB1 (1.5f)
#define KB2 (-3.0f)
#define KB3 (11.0f/6.0f)

#define IT 8
#define A_INT_Y 254   // amper interior i-slices: i0 = 5 + 8*y, i in [5,2036]
#define A_BND_Y 27    // 17 row strips + 10 col strips
#define F_INT_Y 255   // faraday interior i-slices: i0 = 2 + 8*y, i in [2,2041]
#define F_BND_Y 13    // 8 row strips + 5 col strips

__device__ __forceinline__ void load_M(float beta, float delta, float gamma,
                                       float& a0, float& a1,
                                       float& m01, float& m11, float& m21) {
    a0  = -0.25f * beta + 0.1f * gamma;
    a1  =  0.25f * beta - 0.1f * gamma;
    m01 =  0.25f * beta + delta - 0.5f - 0.1f * gamma;
    m11 = -2.0f * delta;
    m21 = -0.25f * beta + delta + 0.5f + 0.1f * gamma;
}

// ===========================================================================
// Scalar point functions (verified) — boundary strips.
// ===========================================================================
__device__ void amper_point(int i, int j,
                            const float* __restrict__ Eb,
                            const float* __restrict__ Hxb,
                            const float* __restrict__ Hyb,
                            float a0, float a1, float m01, float m11, float m21,
                            float* __restrict__ Eob) {
    const bool ic = (i >= 2 && i <= NE - 3);
    const bool jc = (j >= 2 && j <= NE - 3);
    float s1 = 0.0f, s2 = 0.0f;

    if (ic && jc) {
        const float* r0 = Hyb + (size_t)(i - 2) * NW + (j - 2);
        const float* r1 = r0 + NW;
        const float* r2 = r1 + NW;
        const float* r3 = r2 + NW;
        s1 += a0  * r0[0] + a1  * r0[2]
            + m01 * r1[0] + m11 * r1[1] + m21 * r1[2]
            + a1  * r2[0] + a0  * r2[2]
            + a0  * r3[0] + a1  * r3[2];
        const float* x0 = Hxb + (size_t)(i - 2) * NH + (j - 2);
        const float* x1 = x0 + NH;
        const float* x2 = x1 + NH;
        s2 += a0 * x0[0] + m01 * x0[1] + a1 * x0[2] + a0 * x0[3]
            + m11 * x1[1]
            + a1 * x2[0] + m21 * x2[1] + a0 * x2[2] + a1 * x2[3];
    }
    if (i >= 1 && j <= NE - 6) {
        const float* r = Hyb + (size_t)(i - 1) * NW + j;
        s1 += KF0 * r[0] + KF1 * r[1] + KF2 * r[2] + KF3 * r[3];
    }
    if (i <= NE - 2 && j >= 5) {
        const float* r = Hyb + (size_t)i * NW + (j - 5);
        s1 += KB0 * r[0] + KB1 * r[1] + KB2 * r[2] + KB3 * r[3];
    }
    if (ic && (j == 1 || j == 2)) {
        const float* r = Hyb + (size_t)(i - 1) * NW + (j - 1);
        s1 += -r[0] + 3.0f * r[1] - 3.0f * r[2] + r[3];
    }
    if (ic && (j == NE - 3 || j == NE - 2)) {
        const float* r = Hyb + (size_t)i * NW + (j - 4);
        s1 += r[0] - 3.0f * r[1] + 3.0f * r[2] - r[3];
    }
    if (i <= NE - 6 && j >= 1) {
        const float* x = Hxb + (size_t)i * NH + (j - 1);
        s2 += KF0 * x[0] + KF1 * x[NH] + KF2 * x[2 * NH] + KF3 * x[3 * NH];
    }
    if (i >= 5 && j <= NE - 2) {
        const float* x = Hxb + (size_t)(i - 5) * NH + j;
        s2 += KB0 * x[0] + KB1 * x[NH] + KB2 * x[2 * NH] + KB3 * x[3 * NH];
    }
    if ((i == 1 || i == 2) && jc) {
        const float* x = Hxb + (size_t)(i - 1) * NH + (j - 1);
        s2 += -x[0] + 3.0f * x[NH] - 3.0f * x[2 * NH] + x[3 * NH];
    }
    if ((i == NE - 3 || i == NE - 2) && jc) {
        const float* x = Hxb + (size_t)(i - 4) * NH + j;
        s2 += x[0] - 3.0f * x[NH] + 3.0f * x[2 * NH] - x[3 * NH];
    }
    Eob[(size_t)i * NE + j] = Eb[(size_t)i * NE + j] + CFLf * (s1 - s2);
}

__device__ void faraday_point(int i, int j,
                              const float* __restrict__ Eb,
                              const float* __restrict__ Hxb,
                              const float* __restrict__ Hyb,
                              float a0, float a1, float m01, float m11, float m21,
                              float* __restrict__ Hxob,
                              float* __restrict__ Hyob) {
    if (i < NW && j < NH) {
        float s3 = 0.0f;
        if (j >= 1 && j <= NH - 2) {
            const float* e0 = Eb + (size_t)i * NE + (j - 1);
            const float* e1 = e0 + NE;
            const float* e2 = e1 + NE;
            s3 += a0 * e0[0] + m01 * e0[1] + a1 * e0[2] + a0 * e0[3]
                + m11 * e1[1]
                + a1 * e2[0] + m21 * e2[1] + a0 * e2[2] + a1 * e2[3];
        }
        if (i <= NH - 4) {
            const float* e = Eb + (size_t)(i + 1) * NE + j;
            s3 += -1.5f * e[0] + 2.0f * e[NE] - 0.5f * e[2 * NE];
        }
        if (i >= 2) {
            const float* e = Eb + (size_t)(i - 1) * NE + (j + 1);
            s3 += 0.5f * e[0] - 2.0f * e[NE] + 1.5f * e[2 * NE];
        }
        const size_t off = (size_t)i * NH + j;
        Hxob[off] = Hxb[off] - CFLf * s3;
    }
    if (i < NH && j < NW) {
        float s4 = 0.0f;
        if (i >= 1 && i <= NH - 2) {
            const float* e0 = Eb + (size_t)(i - 1) * NE + j;
            const float* e1 = e0 + NE;
            const float* e2 = e1 + NE;
            const float* e3 = e2 + NE;
            s4 += a0  * e0[0] + a1  * e0[2]
                + m01 * e1[0] + m11 * e1[1] + m21 * e1[2]
                + a1  * e2[0] + a0  * e2[2]
                + a0  * e3[0] + a1  * e3[2];
        }
        if (j <= NH - 4) {
            const float* e = Eb + (size_t)i * NE + (j + 1);
            s4 += -1.5f * e[0] + 2.0f * e[1] - 0.5f * e[2];
        }
        if (j >= 2) {
            const float* e = Eb + (size_t)(i + 1) * NE + (j - 1);
            s4 += 0.5f * e[0] - 2.0f * e[1] + 1.5f * e[2];
        }
        const size_t off = (size_t)i * NW + j;
        Hyob[off] = Hyb[off] + CFLf * s4;
    }
}

// ===========================================================================
// Fused amper: interior slices (blockIdx.y < A_INT_Y) + boundary strips.
// ===========================================================================
__global__ __launch_bounds__(256)
void amper_kernel(const float* __restrict__ E,
                  const float* __restrict__ Hx,
                  const float* __restrict__ Hy,
                  const float* __restrict__ pb,
                  const float* __restrict__ pd,
                  const float* __restrict__ pg,
                  float* __restrict__ Eo) {
    const int b = blockIdx.z;
    float a0, a1, m01, m11, m21;
    load_M(*pb, *pd, *pg, a0, a1, m01, m11, m21);

    const float* Eb  = E  + (size_t)b * NE * NE;
    const float* Hxb = Hx + (size_t)b * NW * NH;
    const float* Hyb = Hy + (size_t)b * NH * NW;
    float* Eob = Eo + (size_t)b * NE * NE;

    if (blockIdx.y >= A_INT_Y) {
        // ---- boundary strips ----
        const int y = blockIdx.y - A_INT_Y;
        if (y < 17) {
            const int i = (y < 5) ? y : 2037 + (y - 5);
            const int j = blockIdx.x * 256 + threadIdx.x;
            if (j >= NE) return;
            amper_point(i, j, Eb, Hxb, Hyb, a0, a1, m01, m11, m21, Eob);
        } else {
            const int c = y - 17;
            const int j = (c < 5) ? c : 2044 + (c - 5);
            const int i = 5 + blockIdx.x * 256 + threadIdx.x;
            if (i > 2036) return;
            amper_point(i, j, Eb, Hxb, Hyb, a0, a1, m01, m11, m21, Eob);
        }
        return;
    }

    // ---- interior: i0 = 5 + 8*y, j in [5, 2043] ----
    const int j = 5 + blockIdx.x * 256 + threadIdx.x;
    if (j > 2043) return;
    const int i0 = 5 + blockIdx.y * IT;

    const float a1k  = a1 + KB3;
    const float m21k = m21 + KF0;

    float acc[IT];
#pragma unroll
    for (int k = 0; k < IT; k++) acc[k] = 0.0f;

    // ---- s1: Hy rows r = i0-2 .. i0+8, cols j-5 .. j+3 ----
    {
        const float* hy = Hyb + (size_t)(i0 - 2) * NW + (j - 5);
#pragma unroll
        for (int rr = 0; rr < IT + 3; ++rr) {
            const bool uA = (rr <= IT - 1);
            const bool uB = (rr >= 1 && rr <= IT);
            const bool uC = (rr >= 2 && rr <= IT + 1);
            const bool uD = (rr >= 3);
            float c0 = 0.f, c1 = 0.f, c2 = 0.f, c4 = 0.f, c6 = 0.f, c7 = 0.f, c8 = 0.f;
            const float c3 = hy[3];
            const float c5 = hy[5];
            if (uC) { c0 = hy[0]; c1 = hy[1]; c2 = hy[2]; }
            if (uB) { c4 = hy[4]; c6 = hy[6]; c7 = hy[7]; c8 = hy[8]; }
            const float t = a0 * c3 + a1 * c5;
            if (uA) acc[rr]     += t;
            if (uB) acc[rr - 1] += m01 * c3 + m11 * c4 + m21k * c5
                                 + KF1 * c6 + KF2 * c7 + KF3 * c8;
            if (uC) acc[rr - 2] += KB0 * c0 + KB1 * c1 + KB2 * c2
                                 + a1k * c3 + a0 * c5;
            if (uD) acc[rr - 3] += t;
            hy += NW;
        }
    }

    // ---- s2 (subtract): Hx rows r = i0-5 .. i0+10, cols j-2 .. j+1 ----
    {
        const float* hx = Hxb + (size_t)(i0 - 5) * NH + (j - 2);
#pragma unroll
        for (int rr = 0; rr < IT + 8; ++rr) {
            const bool vK0 = (rr <= IT - 1);
            const bool vK1 = (rr >= 1 && rr <= IT);
            const bool vK2 = (rr >= 2 && rr <= IT + 1);
            const bool vA  = (rr >= 3 && rr <= IT + 2);
            const bool vB  = (rr >= 4 && rr <= IT + 3);
            const bool vC  = (rr >= 5 && rr <= IT + 4);
            const bool vD  = (rr >= 6 && rr <= IT + 5);
            const bool vE  = (rr >= 7 && rr <= IT + 6);
            const bool vF  = (rr >= 8);
            float d0 = 0.f, d1 = 0.f, d2 = 0.f, d3 = 0.f;
            if (vA | vC) { d0 = hx[0]; d3 = hx[3]; }
            if (vA | vB | vC | vD | vE | vF) d1 = hx[1];
            if (vK0 | vK1 | vK2 | vA | vC) d2 = hx[2];
            if (vK0) acc[rr]     -= KB0 * d2;
            if (vK1) acc[rr - 1] -= KB1 * d2;
            if (vK2) acc[rr - 2] -= KB2 * d2;
            if (vA)  acc[rr - 3] -= a0 * d0 + m01 * d1 + a1k * d2 + a0 * d3;
            if (vB)  acc[rr - 4] -= m11 * d1;
            if (vC)  acc[rr - 5] -= a1 * d0 + m21k * d1 + a0 * d2 + a1 * d3;
            if (vD)  acc[rr - 6] -= KF1 * d1;
            if (vE)  acc[rr - 7] -= KF2 * d1;
            if (vF)  acc[rr - 8] -= KF3 * d1;
            hx += NH;
        }
    }

    const size_t off = (size_t)i0 * NE + j;
#pragma unroll
    for (int k = 0; k < IT; k++)
        Eob[off + (size_t)k * NE] = Eb[off + (size_t)k * NE] + CFLf * acc[k];
}

// ===========================================================================
// Fused faraday (Hx+Hy): interior slices + boundary strips.
// ===========================================================================
__global__ __launch_bounds__(256)
void faraday_kernel(const float* __restrict__ E,
                    const float* __restrict__ Hx,
                    const float* __restrict__ Hy,
                    const float* __restrict__ pb,
                    const float* __restrict__ pd,
                    const float* __restrict__ pg,
                    float* __restrict__ Hxo,
                    float* __restrict__ Hyo) {
    const int b = blockIdx.z;
    float a0, a1, m01, m11, m21;
    load_M(*pb, *pd, *pg, a0, a1, m01, m11, m21);

    const float* Eb  = E  + (size_t)b * NE * NE;
    const float* Hxb = Hx + (size_t)b * NW * NH;
    const float* Hyb = Hy + (size_t)b * NH * NW;
    float* Hxob = Hxo + (size_t)b * NW * NH;
    float* Hyob = Hyo + (size_t)b * NH * NW;

    if (blockIdx.y >= F_INT_Y) {
        // ---- boundary strips ----
        const int y = blockIdx.y - F_INT_Y;
        if (y < 8) {
            const int i = (y < 2) ? y : 2042 + (y - 2);
            const int j = blockIdx.x * 256 + threadIdx.x;
            if (j >= NH) return;
            faraday_point(i, j, Eb, Hxb, Hyb, a0, a1, m01, m11, m21, Hxob, Hyob);
        } else {
            const int c = y - 8;
            const int j = (c < 2) ? c : 2045 + (c - 2);
            const int i = 2 + blockIdx.x * 256 + threadIdx.x;
            if (i > 2041) return;
            faraday_point(i, j, Eb, Hxb, Hyb, a0, a1, m01, m11, m21, Hxob, Hyob);
        }
        return;
    }

    // ---- interior: i0 = 2 + 8*y, j in [2, 2044] ----
    const int j = 2 + blockIdx.x * 256 + threadIdx.x;
    if (j > 2044) return;
    const int i0 = 2 + blockIdx.y * IT;

    const float m11b = m11 - 1.5f;
    const float m21b = m21 + 2.0f;
    const float a1m2 = a1 - 2.0f;

    float sx[IT], sy[IT];
#pragma unroll
    for (int k = 0; k < IT; k++) { sx[k] = 0.0f; sy[k] = 0.0f; }

    const float* ep = Eb + (size_t)(i0 - 1) * NE + (j - 1);
#pragma unroll
    for (int rr = 0; rr < IT + 4; ++rr) {
        const bool w0 = (rr <= IT - 1);
        const bool w1 = (rr >= 1 && rr <= IT);
        const bool w2 = (rr >= 2 && rr <= IT + 1);
        const bool w3 = (rr >= 3 && rr <= IT + 2);
        const bool w4 = (rr >= 4);
        float e0 = 0.f, e2 = 0.f, e3 = 0.f, e4 = 0.f;
        const float e1 = ep[1];
        if (w1 | w2 | w3) e0 = ep[0];
        if (w0 | w1 | w2 | w3) { e2 = ep[2]; e3 = ep[3]; }
        if (w1) e4 = ep[4];

        const float ty = a0 * e1 + a1 * e3;
        if (w0) { sx[rr] += 0.5f * e2; sy[rr] += ty; }
        if (w1) {
            sx[rr - 1] += a0 * e0 + m01 * e1 + a1m2 * e2 + a0 * e3;
            sy[rr - 1] += m01 * e1 + m11b * e2 + m21b * e3 - 0.5f * e4;
        }
        if (w2) {
            sx[rr - 2] += m11b * e1 + 1.5f * e2;
            sy[rr - 2] += 0.5f * e0 + a1m2 * e1 + 1.5f * e2 + a0 * e3;
        }
        if (w3) {
            sx[rr - 3] += a1 * e0 + m21b * e1 + a0 * e2 + a1 * e3;
            sy[rr - 3] += ty;
        }
        if (w4) sx[rr - 4] -= 0.5f * e1;
        ep += NE;
    }

    const size_t offx = (size_t)i0 * NH + j;
    const size_t offy = (size_t)i0 * NW + j;
#pragma unroll
    for (int k = 0; k < IT; k++) {
        Hxob[offx + (size_t)k * NH] = Hxb[offx + (size_t)k * NH] - CFLf * sx[k];
        Hyob[offy + (size_t)k * NW] = Hyb[offy + (size_t)k * NW] + CFLf * sy[k];
    }
}

// ===========================================================================
extern "C" void kernel_launch(void* const* d_in, const int* in_sizes, int n_in,
                              void* d_out, int out_size) {
    const float* E0  = (const float*)d_in[0];
    const float* Hx0 = (const float*)d_in[1];
    const float* Hy0 = (const float*)d_in[2];
    const float* pb  = (const float*)d_in[3];
    const float* pd  = (const float*)d_in[4];
    const float* pg  = (const float*)d_in[5];

    const int B = in_sizes[0] / (NE * NE);

    const size_t nE  = (size_t)B * NE * NE;
    const size_t nHx = (size_t)B * NW * NH;
    const size_t nHy = (size_t)B * NH * NW;

    float* out = (float*)d_out;
    float* E2  = out;
    float* Hx2 = E2 + nE;
    float* Hy2 = Hx2 + nHx;
    float* E3  = Hy2 + nHy;
    float* Hx3 = E3 + nE;
    float* Hy3 = Hx3 + nHx;
    float* E4  = Hy3 + nHy;
    float* Hx4 = E4 + nE;
    float* Hy4 = Hx4 + nHx;

    dim3 blk(256);
    // amper: x=9 covers boundary rows (2049 cols); interior uses x<8 (j<=2043).
    dim3 gA(9, A_INT_Y + A_BND_Y, B);
    // faraday: x=8 covers both interior (j<=2044) and boundary (2048 cols).
    dim3 gF(8, F_INT_Y + F_BND_Y, B);

    const float* Ein  = E0;
    const float* Hxin = Hx0;
    const float* Hyin = Hy0;
    float* Eouts[3]  = {E2, E3, E4};
    float* Hxouts[3] = {Hx2, Hx3, Hx4};
    float* Hyouts[3] = {Hy2, Hy3, Hy4};

    for (int s = 0; s < 3; s++) {
        amper_kernel<<<gA, blk>>>(Ein, Hxin, Hyin, pb, pd, pg, Eouts[s]);
        faraday_kernel<<<gF, blk>>>(Eouts[s], Hxin, Hyin, pb, pd, pg,
                                    Hxouts[s], Hyouts[s]);
        Ein = Eouts[s]; Hxin = Hxouts[s]; Hyin = Hyouts[s];
    }
}